// round 9
// baseline (speedup 1.0000x reference)
#include <cuda_runtime.h>
#include <cuda_bf16.h>
#include <cstdint>

#define N_RAYS 32768
#define M_G    1024
#define NTILES (M_G / 8)       // 128 n-tiles of 8 gaussians
#define WARPS  8
#define RAYS_PER_WARP 16
#define RAYS_PER_BLOCK (WARPS * RAYS_PER_WARP)   // 128

typedef unsigned int u32;
typedef unsigned long long ull;

// B fragment table in m16n8k16 lane layout, deduplicated:
//   g_tblB[(t*2 + s)*32 + lane], s=0 -> hi coefficients, s=1 -> lo.
__device__ __align__(16) ull g_tblB[NTILES * 2 * 32];   // 64 KB

// Permuted labels: for round r (pair of tiles 2r, 2r+1) and tig (0..3):
//   g_plab[r*16 + tig*4 + {0,1}] = labels[(2r)*8 + 2*tig + {0,1}]
//   g_plab[r*16 + tig*4 + {2,3}] = labels[(2r+1)*8 + 2*tig + {0,1}]
__device__ __align__(16) float g_plab[M_G];

__device__ __forceinline__ u32 pack_bf16x2(float a, float b) {
    __nv_bfloat16 x = __float2bfloat16(a), y = __float2bfloat16(b);
    return (u32)__bfloat16_as_ushort(x) | ((u32)__bfloat16_as_ushort(y) << 16);
}

// ---------------------------------------------------------------------------
// Prep: invert Sigma (fp32 GJ + one Newton step), fold -0.5*log2(e) and mean
// into 16 coefficients, split bf16 hi/lo, emit B fragments + permuted labels.
// ---------------------------------------------------------------------------
__global__ void prep_kernel(const float* __restrict__ means,
                            const float* __restrict__ covs,
                            const float* __restrict__ labels) {
    int m = blockIdx.x * blockDim.x + threadIdx.x;
    if (m >= M_G) return;

    float S[4][4], a[4][8];
    #pragma unroll
    for (int i = 0; i < 4; i++)
        #pragma unroll
        for (int j = 0; j < 4; j++) {
            S[i][j] = covs[m * 16 + i * 4 + j];
            a[i][j] = S[i][j];
        }
    #pragma unroll
    for (int i = 0; i < 4; i++)
        #pragma unroll
        for (int j = 0; j < 4; j++) a[i][4 + j] = (i == j) ? 1.0f : 0.0f;
    #pragma unroll
    for (int c = 0; c < 4; c++) {
        float inv = __frcp_rn(a[c][c]);
        #pragma unroll
        for (int j = 0; j < 8; j++) a[c][j] *= inv;
        #pragma unroll
        for (int r = 0; r < 4; r++) {
            if (r == c) continue;
            float f = a[r][c];
            #pragma unroll
            for (int j = 0; j < 8; j++) a[r][j] = fmaf(-f, a[c][j], a[r][j]);
        }
    }
    float X[4][4], T[4][4], Xr[4][4];
    #pragma unroll
    for (int i = 0; i < 4; i++)
        #pragma unroll
        for (int j = 0; j < 4; j++) X[i][j] = a[i][4 + j];
    #pragma unroll
    for (int i = 0; i < 4; i++)
        #pragma unroll
        for (int j = 0; j < 4; j++) {
            float s = (i == j) ? 2.0f : 0.0f;
            #pragma unroll
            for (int k = 0; k < 4; k++) s = fmaf(-S[i][k], X[k][j], s);
            T[i][j] = s;
        }
    #pragma unroll
    for (int i = 0; i < 4; i++)
        #pragma unroll
        for (int j = 0; j < 4; j++) {
            float s = 0.0f;
            #pragma unroll
            for (int k = 0; k < 4; k++) s = fmaf(X[i][k], T[k][j], s);
            Xr[i][j] = s;
        }
    const float kk = -0.5f * 1.4426950408889634f;   // -0.5*log2(e)
    float C[4][4];
    #pragma unroll
    for (int i = 0; i < 4; i++)
        #pragma unroll
        for (int j = 0; j < 4; j++) C[i][j] = kk * Xr[i][j];
    float mu[4];
    #pragma unroll
    for (int i = 0; i < 4; i++) mu[i] = means[m * 4 + i];

    float w[16];
    w[0] = C[0][0]; w[1] = C[1][1]; w[2] = C[2][2]; w[3] = C[3][3];
    w[4] = 2.0f * C[0][1]; w[5] = 2.0f * C[0][2]; w[6] = 2.0f * C[0][3];
    w[7] = 2.0f * C[1][2]; w[8] = 2.0f * C[1][3]; w[9] = 2.0f * C[2][3];
    #pragma unroll
    for (int i = 0; i < 4; i++) {
        float s = 0.0f;
        #pragma unroll
        for (int j = 0; j < 4; j++) s = fmaf(C[i][j], mu[j], s);
        w[10 + i] = -2.0f * s;
    }
    float q = 0.0f;
    #pragma unroll
    for (int i = 0; i < 4; i++) {
        float s = 0.0f;
        #pragma unroll
        for (int j = 0; j < 4; j++) s = fmaf(C[i][j], mu[j], s);
        q = fmaf(mu[i], s, q);
    }
    w[14] = q;
    w[15] = 0.0f;

    float hi[16], lo[16];
    #pragma unroll
    for (int k = 0; k < 16; k++) {
        __nv_bfloat16 h = __float2bfloat16(w[k]);
        hi[k] = __bfloat162float(h);
        lo[k] = w[k] - hi[k];
    }

    const int t = m >> 3, j = m & 7;
    #pragma unroll
    for (int tig = 0; tig < 4; tig++) {
        u32 h0 = pack_bf16x2(hi[2 * tig],     hi[2 * tig + 1]);
        u32 h1 = pack_bf16x2(hi[2 * tig + 8], hi[2 * tig + 9]);
        u32 l0 = pack_bf16x2(lo[2 * tig],     lo[2 * tig + 1]);
        u32 l1 = pack_bf16x2(lo[2 * tig + 8], lo[2 * tig + 9]);
        const int lane = 4 * j + tig;
        g_tblB[(t * 2 + 0) * 32 + lane] = (ull)h0 | ((ull)h1 << 32);  // hi
        g_tblB[(t * 2 + 1) * 32 + lane] = (ull)l0 | ((ull)l1 << 32);  // lo
    }

    // permuted label: gaussian m = t*8 + 2*tig + p  (p = j&1, tig = (j>>1))
    {
        const int r = t >> 1, odd = t & 1, tg = j >> 1, p = j & 1;
        g_plab[r * 16 + tg * 4 + odd * 2 + p] = labels[m];
    }
}

// ---------------------------------------------------------------------------
// Decoder: 256 threads = 8 warps x 16 rays; 64 rounds of 2 interleaved
// n-tiles (6 MMAs, 8 ex2, 8 FMA per round), unroll 2 -> 4 tiles in flight.
// ---------------------------------------------------------------------------
#define SM_TBL   0
#define SM_LAB   (NTILES * 2 * 32 * 8)               // 65536
#define SM_STAGE (SM_LAB + M_G * 4)                  // 69632
#define STAGE_W  25
#define SM_TOTAL (SM_STAGE + RAYS_PER_BLOCK * STAGE_W * 4)  // 82432

extern __shared__ unsigned char smem_raw[];

__device__ __forceinline__ void mma16816(float& c0, float& c1, float& c2, float& c3,
                                         u32 a0, u32 a1, u32 a2, u32 a3,
                                         u32 b0, u32 b1) {
    asm volatile(
        "mma.sync.aligned.m16n8k16.row.col.f32.bf16.bf16.f32 "
        "{%0,%1,%2,%3}, {%4,%5,%6,%7}, {%8,%9}, {%0,%1,%2,%3};"
        : "+f"(c0), "+f"(c1), "+f"(c2), "+f"(c3)
        : "r"(a0), "r"(a1), "r"(a2), "r"(a3), "r"(b0), "r"(b1));
}

__global__ void __launch_bounds__(256, 2)
decoder_kernel(const float* __restrict__ origins,
               const float* __restrict__ dirs,
               float* __restrict__ out) {
    const int tid  = threadIdx.x;
    const int wid  = tid >> 5;
    const int lane = tid & 31;
    const int gid  = lane >> 2;   // row group 0..7
    const int tig  = lane & 3;    // thread-in-group

    // ---- cooperative copies: B table (64KB) + permuted labels (4KB) ----
    {
        const uint4* gt = reinterpret_cast<const uint4*>(g_tblB);
        uint4* st = reinterpret_cast<uint4*>(smem_raw + SM_TBL);
        #pragma unroll
        for (int i = 0; i < (NTILES * 2 * 32 * 8 / 16) / 256; i++)
            st[tid + i * 256] = gt[tid + i * 256];
        const uint4* gl = reinterpret_cast<const uint4*>(g_plab);
        uint4* sl = reinterpret_cast<uint4*>(smem_raw + SM_LAB);
        sl[tid] = gl[tid];
    }

    // ---- A staging ----
    u32* stage = reinterpret_cast<u32*>(smem_raw + SM_STAGE) +
                 wid * RAYS_PER_WARP * STAGE_W;
    const int ray_base = blockIdx.x * RAYS_PER_BLOCK + wid * RAYS_PER_WARP;
    if (lane < 16) {
        const int n = ray_base + lane;
        const float2 o = reinterpret_cast<const float2*>(origins)[n];
        const float2 d = reinterpret_cast<const float2*>(dirs)[n];
        const float p0 = o.x, p1 = o.y, p2 = d.x, p3 = d.y;
        float phi[16];
        phi[0] = p0 * p0; phi[1] = p1 * p1; phi[2] = p2 * p2; phi[3] = p3 * p3;
        phi[4] = p0 * p1; phi[5] = p0 * p2; phi[6] = p0 * p3;
        phi[7] = p1 * p2; phi[8] = p1 * p3; phi[9] = p2 * p3;
        phi[10] = p0; phi[11] = p1; phi[12] = p2; phi[13] = p3;
        phi[14] = 1.0f; phi[15] = 0.0f;
        float hi[16], lo[16];
        #pragma unroll
        for (int k = 0; k < 16; k++) {
            __nv_bfloat16 h = __float2bfloat16(phi[k]);
            hi[k] = __bfloat162float(h);
            lo[k] = phi[k] - hi[k];
        }
        u32* row = stage + lane * STAGE_W;
        #pragma unroll
        for (int wd = 0; wd < 8; wd++) {
            row[wd]      = pack_bf16x2(hi[2 * wd], hi[2 * wd + 1]);  // hi
            row[8 + wd]  = pack_bf16x2(lo[2 * wd], lo[2 * wd + 1]);  // lo
            row[16 + wd] = row[wd];                                   // hi again
        }
    }
    __syncthreads();

    // ---- load A fragments ----
    u32 afr[3][4];
    #pragma unroll
    for (int s = 0; s < 3; s++) {
        afr[s][0] = stage[gid * STAGE_W       + 8 * s + tig];
        afr[s][1] = stage[(gid + 8) * STAGE_W + 8 * s + tig];
        afr[s][2] = stage[gid * STAGE_W       + 8 * s + tig + 4];
        afr[s][3] = stage[(gid + 8) * STAGE_W + 8 * s + tig + 4];
    }

    const ull* tbl = reinterpret_cast<const ull*>(smem_raw + SM_TBL);
    const float4* lab4 = reinterpret_cast<const float4*>(smem_raw + SM_LAB);

    float acc0 = 0.0f, acc1 = 0.0f, acc2 = 0.0f, acc3 = 0.0f;

    #pragma unroll 2
    for (int r = 0; r < NTILES / 2; r++) {
        // hoisted B loads for both tiles of the round
        const ull* bt = tbl + r * 128 + lane;
        const ull hhx = bt[0];           // tile 2r   hi
        const ull llx = bt[32];          // tile 2r   lo
        const ull hhy = bt[64];          // tile 2r+1 hi
        const ull lly = bt[96];          // tile 2r+1 lo
        const float4 L = lab4[r * 4 + tig];   // {t_even pair, t_odd pair}

        // tile X: chain A (hi*hi) + chain B (lo*hi, hi*lo)
        float xA0 = 0.f, xA1 = 0.f, xA2 = 0.f, xA3 = 0.f;
        float xB0 = 0.f, xB1 = 0.f, xB2 = 0.f, xB3 = 0.f;
        mma16816(xA0, xA1, xA2, xA3, afr[0][0], afr[0][1], afr[0][2], afr[0][3],
                 (u32)hhx, (u32)(hhx >> 32));
        mma16816(xB0, xB1, xB2, xB3, afr[1][0], afr[1][1], afr[1][2], afr[1][3],
                 (u32)hhx, (u32)(hhx >> 32));
        mma16816(xB0, xB1, xB2, xB3, afr[2][0], afr[2][1], afr[2][2], afr[2][3],
                 (u32)llx, (u32)(llx >> 32));

        // tile Y
        float yA0 = 0.f, yA1 = 0.f, yA2 = 0.f, yA3 = 0.f;
        float yB0 = 0.f, yB1 = 0.f, yB2 = 0.f, yB3 = 0.f;
        mma16816(yA0, yA1, yA2, yA3, afr[0][0], afr[0][1], afr[0][2], afr[0][3],
                 (u32)hhy, (u32)(hhy >> 32));
        mma16816(yB0, yB1, yB2, yB3, afr[1][0], afr[1][1], afr[1][2], afr[1][3],
                 (u32)hhy, (u32)(hhy >> 32));
        mma16816(yB0, yB1, yB2, yB3, afr[2][0], afr[2][1], afr[2][2], afr[2][3],
                 (u32)lly, (u32)(lly >> 32));

        float e;
        asm("ex2.approx.ftz.f32 %0, %1;" : "=f"(e) : "f"(xA0 + xB0));
        acc0 = fmaf(L.x, e, acc0);
        asm("ex2.approx.ftz.f32 %0, %1;" : "=f"(e) : "f"(xA1 + xB1));
        acc1 = fmaf(L.y, e, acc1);
        asm("ex2.approx.ftz.f32 %0, %1;" : "=f"(e) : "f"(xA2 + xB2));
        acc2 = fmaf(L.x, e, acc2);
        asm("ex2.approx.ftz.f32 %0, %1;" : "=f"(e) : "f"(xA3 + xB3));
        acc3 = fmaf(L.y, e, acc3);
        asm("ex2.approx.ftz.f32 %0, %1;" : "=f"(e) : "f"(yA0 + yB0));
        acc0 = fmaf(L.z, e, acc0);
        asm("ex2.approx.ftz.f32 %0, %1;" : "=f"(e) : "f"(yA1 + yB1));
        acc1 = fmaf(L.w, e, acc1);
        asm("ex2.approx.ftz.f32 %0, %1;" : "=f"(e) : "f"(yA2 + yB2));
        acc2 = fmaf(L.z, e, acc2);
        asm("ex2.approx.ftz.f32 %0, %1;" : "=f"(e) : "f"(yA3 + yB3));
        acc3 = fmaf(L.w, e, acc3);
    }

    float accLo = acc0 + acc1;   // ray gid
    float accHi = acc2 + acc3;   // ray gid+8

    #pragma unroll
    for (int d = 1; d < 4; d <<= 1) {
        accLo += __shfl_xor_sync(0xffffffffu, accLo, d);
        accHi += __shfl_xor_sync(0xffffffffu, accHi, d);
    }

    if (tig == 0) {
        const float zL = -accLo * 1.4426950408889634f;
        const float zH = -accHi * 1.4426950408889634f;
        float eL, eH, pL, pH;
        asm("ex2.approx.ftz.f32 %0, %1;" : "=f"(eL) : "f"(zL));
        asm("ex2.approx.ftz.f32 %0, %1;" : "=f"(eH) : "f"(zH));
        asm("rcp.approx.ftz.f32 %0, %1;" : "=f"(pL) : "f"(1.0f + eL));
        asm("rcp.approx.ftz.f32 %0, %1;" : "=f"(pH) : "f"(1.0f + eH));
        out[ray_base + gid]     = pL;
        out[ray_base + gid + 8] = pH;
    }
}

// ---------------------------------------------------------------------------
extern "C" void kernel_launch(void* const* d_in, const int* in_sizes, int n_in,
                              void* d_out, int out_size) {
    const float* origins    = (const float*)d_in[0];
    const float* directions = (const float*)d_in[1];
    const float* means      = (const float*)d_in[2];
    const float* covs       = (const float*)d_in[3];
    const float* labels     = (const float*)d_in[4];
    float* out = (float*)d_out;

    prep_kernel<<<8, 128>>>(means, covs, labels);

    cudaFuncSetAttribute(decoder_kernel,
                         cudaFuncAttributeMaxDynamicSharedMemorySize, SM_TOTAL);
    decoder_kernel<<<N_RAYS / RAYS_PER_BLOCK, 256, SM_TOTAL>>>(
        origins, directions, out);
}

// round 10
// speedup vs baseline: 1.0106x; 1.0106x over previous
#include <cuda_runtime.h>
#include <cuda_bf16.h>
#include <cstdint>

#define N_RAYS 32768
#define M_G    1024
#define NTILES (M_G / 8)       // 128 n-tiles of 8 gaussians
#define HALF_TILES (NTILES / 2)
#define HALF_ROUNDS (HALF_TILES / 2)   // 32 rounds of 2 tiles
#define WARPS  8
#define RAYS_PER_WARP 16
#define RAYS_PER_BLOCK (WARPS * RAYS_PER_WARP)   // 128
#define NGROUPS (N_RAYS / RAYS_PER_BLOCK)        // 256 ray-groups

typedef unsigned int u32;
typedef unsigned long long ull;

// B fragment table in m16n8k16 lane layout, deduplicated:
//   g_tblB[(t*2 + s)*32 + lane], s=0 -> hi coefficients, s=1 -> lo.
__device__ __align__(16) ull g_tblB[NTILES * 2 * 32];   // 64 KB

// Permuted labels (per 2-tile round r, tig): see prep.
__device__ __align__(16) float g_plab[M_G];

// Cross-block combine scratch: per-half partial sums + per-group counters.
__device__ float g_part[2 * N_RAYS];
__device__ int   g_cnt[NGROUPS];      // zero-init; self-resetting

__device__ __forceinline__ u32 pack_bf16x2(float a, float b) {
    __nv_bfloat16 x = __float2bfloat16(a), y = __float2bfloat16(b);
    return (u32)__bfloat16_as_ushort(x) | ((u32)__bfloat16_as_ushort(y) << 16);
}

// ---------------------------------------------------------------------------
// Prep: invert Sigma (fp32 GJ + one Newton step), fold -0.5*log2(e) and mean
// into 16 coefficients, split bf16 hi/lo, emit B fragments + permuted labels.
// ---------------------------------------------------------------------------
__global__ void prep_kernel(const float* __restrict__ means,
                            const float* __restrict__ covs,
                            const float* __restrict__ labels) {
    int m = blockIdx.x * blockDim.x + threadIdx.x;
    if (m >= M_G) return;

    float S[4][4], a[4][8];
    #pragma unroll
    for (int i = 0; i < 4; i++)
        #pragma unroll
        for (int j = 0; j < 4; j++) {
            S[i][j] = covs[m * 16 + i * 4 + j];
            a[i][j] = S[i][j];
        }
    #pragma unroll
    for (int i = 0; i < 4; i++)
        #pragma unroll
        for (int j = 0; j < 4; j++) a[i][4 + j] = (i == j) ? 1.0f : 0.0f;
    #pragma unroll
    for (int c = 0; c < 4; c++) {
        float inv = __frcp_rn(a[c][c]);
        #pragma unroll
        for (int j = 0; j < 8; j++) a[c][j] *= inv;
        #pragma unroll
        for (int r = 0; r < 4; r++) {
            if (r == c) continue;
            float f = a[r][c];
            #pragma unroll
            for (int j = 0; j < 8; j++) a[r][j] = fmaf(-f, a[c][j], a[r][j]);
        }
    }
    float X[4][4], T[4][4], Xr[4][4];
    #pragma unroll
    for (int i = 0; i < 4; i++)
        #pragma unroll
        for (int j = 0; j < 4; j++) X[i][j] = a[i][4 + j];
    #pragma unroll
    for (int i = 0; i < 4; i++)
        #pragma unroll
        for (int j = 0; j < 4; j++) {
            float s = (i == j) ? 2.0f : 0.0f;
            #pragma unroll
            for (int k = 0; k < 4; k++) s = fmaf(-S[i][k], X[k][j], s);
            T[i][j] = s;
        }
    #pragma unroll
    for (int i = 0; i < 4; i++)
        #pragma unroll
        for (int j = 0; j < 4; j++) {
            float s = 0.0f;
            #pragma unroll
            for (int k = 0; k < 4; k++) s = fmaf(X[i][k], T[k][j], s);
            Xr[i][j] = s;
        }
    const float kk = -0.5f * 1.4426950408889634f;   // -0.5*log2(e)
    float C[4][4];
    #pragma unroll
    for (int i = 0; i < 4; i++)
        #pragma unroll
        for (int j = 0; j < 4; j++) C[i][j] = kk * Xr[i][j];
    float mu[4];
    #pragma unroll
    for (int i = 0; i < 4; i++) mu[i] = means[m * 4 + i];

    float w[16];
    w[0] = C[0][0]; w[1] = C[1][1]; w[2] = C[2][2]; w[3] = C[3][3];
    w[4] = 2.0f * C[0][1]; w[5] = 2.0f * C[0][2]; w[6] = 2.0f * C[0][3];
    w[7] = 2.0f * C[1][2]; w[8] = 2.0f * C[1][3]; w[9] = 2.0f * C[2][3];
    #pragma unroll
    for (int i = 0; i < 4; i++) {
        float s = 0.0f;
        #pragma unroll
        for (int j = 0; j < 4; j++) s = fmaf(C[i][j], mu[j], s);
        w[10 + i] = -2.0f * s;
    }
    float q = 0.0f;
    #pragma unroll
    for (int i = 0; i < 4; i++) {
        float s = 0.0f;
        #pragma unroll
        for (int j = 0; j < 4; j++) s = fmaf(C[i][j], mu[j], s);
        q = fmaf(mu[i], s, q);
    }
    w[14] = q;
    w[15] = 0.0f;

    float hi[16], lo[16];
    #pragma unroll
    for (int k = 0; k < 16; k++) {
        __nv_bfloat16 h = __float2bfloat16(w[k]);
        hi[k] = __bfloat162float(h);
        lo[k] = w[k] - hi[k];
    }

    const int t = m >> 3, j = m & 7;
    #pragma unroll
    for (int tig = 0; tig < 4; tig++) {
        u32 h0 = pack_bf16x2(hi[2 * tig],     hi[2 * tig + 1]);
        u32 h1 = pack_bf16x2(hi[2 * tig + 8], hi[2 * tig + 9]);
        u32 l0 = pack_bf16x2(lo[2 * tig],     lo[2 * tig + 1]);
        u32 l1 = pack_bf16x2(lo[2 * tig + 8], lo[2 * tig + 9]);
        const int lane = 4 * j + tig;
        g_tblB[(t * 2 + 0) * 32 + lane] = (ull)h0 | ((ull)h1 << 32);  // hi
        g_tblB[(t * 2 + 1) * 32 + lane] = (ull)l0 | ((ull)l1 << 32);  // lo
    }

    // permuted label: gaussian m = t*8 + 2*tig + p  (p = j&1, tig = (j>>1))
    {
        const int r = t >> 1, odd = t & 1, tg = j >> 1, p = j & 1;
        g_plab[r * 16 + tg * 4 + odd * 2 + p] = labels[m];
    }
}

// ---------------------------------------------------------------------------
// Decoder: 512 blocks = 256 ray-groups x 2 gaussian-halves. 8 warps x 16 rays.
// Each block: 32 KB half-table in SMEM, 32 rounds of 2 interleaved n-tiles.
// Second-arriving block of each pair combines partials + sigmoid (threadfence
// reduction pattern), then resets the counter for graph replay.
// ---------------------------------------------------------------------------
#define SM_TBL   0
#define SM_LAB   (HALF_TILES * 2 * 32 * 8)           // 32768
#define SM_STAGE (SM_LAB + (M_G / 2) * 4)            // 34816
#define STAGE_W  25
#define SM_FLAG  (SM_STAGE + RAYS_PER_BLOCK * STAGE_W * 4)  // 47616
#define SM_TOTAL (SM_FLAG + 16)

extern __shared__ unsigned char smem_raw[];

__device__ __forceinline__ void mma16816(float& c0, float& c1, float& c2, float& c3,
                                         u32 a0, u32 a1, u32 a2, u32 a3,
                                         u32 b0, u32 b1) {
    asm volatile(
        "mma.sync.aligned.m16n8k16.row.col.f32.bf16.bf16.f32 "
        "{%0,%1,%2,%3}, {%4,%5,%6,%7}, {%8,%9}, {%0,%1,%2,%3};"
        : "+f"(c0), "+f"(c1), "+f"(c2), "+f"(c3)
        : "r"(a0), "r"(a1), "r"(a2), "r"(a3), "r"(b0), "r"(b1));
}

__global__ void __launch_bounds__(256, 3)
decoder_kernel(const float* __restrict__ origins,
               const float* __restrict__ dirs,
               float* __restrict__ out) {
    const int tid  = threadIdx.x;
    const int wid  = tid >> 5;
    const int lane = tid & 31;
    const int gid  = lane >> 2;   // row group 0..7
    const int tig  = lane & 3;    // thread-in-group
    const int rg   = blockIdx.x >> 1;   // ray group
    const int hf   = blockIdx.x & 1;    // gaussian half

    // ---- cooperative copies: half table (32KB) + half labels (2KB) ----
    {
        const uint4* gt = reinterpret_cast<const uint4*>(g_tblB + hf * (HALF_TILES * 2 * 32));
        uint4* st = reinterpret_cast<uint4*>(smem_raw + SM_TBL);
        #pragma unroll
        for (int i = 0; i < (HALF_TILES * 2 * 32 * 8 / 16) / 256; i++)
            st[tid + i * 256] = gt[tid + i * 256];
        if (tid < 128) {
            const uint4* gl = reinterpret_cast<const uint4*>(g_plab + hf * (M_G / 2));
            uint4* sl = reinterpret_cast<uint4*>(smem_raw + SM_LAB);
            sl[tid] = gl[tid];
        }
    }

    // ---- A staging ----
    u32* stage = reinterpret_cast<u32*>(smem_raw + SM_STAGE) +
                 wid * RAYS_PER_WARP * STAGE_W;
    const int ray_base = rg * RAYS_PER_BLOCK + wid * RAYS_PER_WARP;
    if (lane < 16) {
        const int n = ray_base + lane;
        const float2 o = reinterpret_cast<const float2*>(origins)[n];
        const float2 d = reinterpret_cast<const float2*>(dirs)[n];
        const float p0 = o.x, p1 = o.y, p2 = d.x, p3 = d.y;
        float phi[16];
        phi[0] = p0 * p0; phi[1] = p1 * p1; phi[2] = p2 * p2; phi[3] = p3 * p3;
        phi[4] = p0 * p1; phi[5] = p0 * p2; phi[6] = p0 * p3;
        phi[7] = p1 * p2; phi[8] = p1 * p3; phi[9] = p2 * p3;
        phi[10] = p0; phi[11] = p1; phi[12] = p2; phi[13] = p3;
        phi[14] = 1.0f; phi[15] = 0.0f;
        float hi[16], lo[16];
        #pragma unroll
        for (int k = 0; k < 16; k++) {
            __nv_bfloat16 h = __float2bfloat16(phi[k]);
            hi[k] = __bfloat162float(h);
            lo[k] = phi[k] - hi[k];
        }
        u32* row = stage + lane * STAGE_W;
        #pragma unroll
        for (int wd = 0; wd < 8; wd++) {
            row[wd]      = pack_bf16x2(hi[2 * wd], hi[2 * wd + 1]);  // hi
            row[8 + wd]  = pack_bf16x2(lo[2 * wd], lo[2 * wd + 1]);  // lo
            row[16 + wd] = row[wd];                                   // hi again
        }
    }
    __syncthreads();

    // ---- load A fragments ----
    u32 afr[3][4];
    #pragma unroll
    for (int s = 0; s < 3; s++) {
        afr[s][0] = stage[gid * STAGE_W       + 8 * s + tig];
        afr[s][1] = stage[(gid + 8) * STAGE_W + 8 * s + tig];
        afr[s][2] = stage[gid * STAGE_W       + 8 * s + tig + 4];
        afr[s][3] = stage[(gid + 8) * STAGE_W + 8 * s + tig + 4];
    }

    const ull* tbl = reinterpret_cast<const ull*>(smem_raw + SM_TBL);
    const float4* lab4 = reinterpret_cast<const float4*>(smem_raw + SM_LAB);

    float acc0 = 0.0f, acc1 = 0.0f, acc2 = 0.0f, acc3 = 0.0f;

    #pragma unroll 2
    for (int r = 0; r < HALF_ROUNDS; r++) {
        const ull* bt = tbl + r * 128 + lane;
        const ull hhx = bt[0];
        const ull llx = bt[32];
        const ull hhy = bt[64];
        const ull lly = bt[96];
        const float4 L = lab4[r * 4 + tig];

        float xA0 = 0.f, xA1 = 0.f, xA2 = 0.f, xA3 = 0.f;
        float xB0 = 0.f, xB1 = 0.f, xB2 = 0.f, xB3 = 0.f;
        mma16816(xA0, xA1, xA2, xA3, afr[0][0], afr[0][1], afr[0][2], afr[0][3],
                 (u32)hhx, (u32)(hhx >> 32));
        mma16816(xB0, xB1, xB2, xB3, afr[1][0], afr[1][1], afr[1][2], afr[1][3],
                 (u32)hhx, (u32)(hhx >> 32));
        mma16816(xB0, xB1, xB2, xB3, afr[2][0], afr[2][1], afr[2][2], afr[2][3],
                 (u32)llx, (u32)(llx >> 32));

        float yA0 = 0.f, yA1 = 0.f, yA2 = 0.f, yA3 = 0.f;
        float yB0 = 0.f, yB1 = 0.f, yB2 = 0.f, yB3 = 0.f;
        mma16816(yA0, yA1, yA2, yA3, afr[0][0], afr[0][1], afr[0][2], afr[0][3],
                 (u32)hhy, (u32)(hhy >> 32));
        mma16816(yB0, yB1, yB2, yB3, afr[1][0], afr[1][1], afr[1][2], afr[1][3],
                 (u32)hhy, (u32)(hhy >> 32));
        mma16816(yB0, yB1, yB2, yB3, afr[2][0], afr[2][1], afr[2][2], afr[2][3],
                 (u32)lly, (u32)(lly >> 32));

        float e;
        asm("ex2.approx.ftz.f32 %0, %1;" : "=f"(e) : "f"(xA0 + xB0));
        acc0 = fmaf(L.x, e, acc0);
        asm("ex2.approx.ftz.f32 %0, %1;" : "=f"(e) : "f"(xA1 + xB1));
        acc1 = fmaf(L.y, e, acc1);
        asm("ex2.approx.ftz.f32 %0, %1;" : "=f"(e) : "f"(xA2 + xB2));
        acc2 = fmaf(L.x, e, acc2);
        asm("ex2.approx.ftz.f32 %0, %1;" : "=f"(e) : "f"(xA3 + xB3));
        acc3 = fmaf(L.y, e, acc3);
        asm("ex2.approx.ftz.f32 %0, %1;" : "=f"(e) : "f"(yA0 + yB0));
        acc0 = fmaf(L.z, e, acc0);
        asm("ex2.approx.ftz.f32 %0, %1;" : "=f"(e) : "f"(yA1 + yB1));
        acc1 = fmaf(L.w, e, acc1);
        asm("ex2.approx.ftz.f32 %0, %1;" : "=f"(e) : "f"(yA2 + yB2));
        acc2 = fmaf(L.z, e, acc2);
        asm("ex2.approx.ftz.f32 %0, %1;" : "=f"(e) : "f"(yA3 + yB3));
        acc3 = fmaf(L.w, e, acc3);
    }

    float accLo = acc0 + acc1;   // ray gid
    float accHi = acc2 + acc3;   // ray gid+8

    #pragma unroll
    for (int d = 1; d < 4; d <<= 1) {
        accLo += __shfl_xor_sync(0xffffffffu, accLo, d);
        accHi += __shfl_xor_sync(0xffffffffu, accHi, d);
    }

    // ---- publish partials ----
    if (tig == 0) {
        g_part[hf * N_RAYS + ray_base + gid]     = accLo;
        g_part[hf * N_RAYS + ray_base + gid + 8] = accHi;
    }
    __syncthreads();

    // ---- threadfence-reduction: second arriver combines + sigmoids ----
    volatile int* sflag = reinterpret_cast<volatile int*>(smem_raw + SM_FLAG);
    if (tid == 0) {
        __threadfence();
        int old = atomicAdd(&g_cnt[rg], 1);
        *sflag = (old == 1);
    }
    __syncthreads();

    if (*sflag) {
        __threadfence();   // acquire side
        if (tid < RAYS_PER_BLOCK) {
            const int n = rg * RAYS_PER_BLOCK + tid;
            const float s = g_part[n] + g_part[N_RAYS + n];
            const float z = -s * 1.4426950408889634f;
            float em, prob;
            asm("ex2.approx.ftz.f32 %0, %1;" : "=f"(em) : "f"(z));
            asm("rcp.approx.ftz.f32 %0, %1;" : "=f"(prob) : "f"(1.0f + em));
            out[n] = prob;
        }
        __syncthreads();
        if (tid == 0) g_cnt[rg] = 0;   // reset for next graph replay
    }
}

// ---------------------------------------------------------------------------
extern "C" void kernel_launch(void* const* d_in, const int* in_sizes, int n_in,
                              void* d_out, int out_size) {
    const float* origins    = (const float*)d_in[0];
    const float* directions = (const float*)d_in[1];
    const float* means      = (const float*)d_in[2];
    const float* covs       = (const float*)d_in[3];
    const float* labels     = (const float*)d_in[4];
    float* out = (float*)d_out;

    prep_kernel<<<8, 128>>>(means, covs, labels);

    cudaFuncSetAttribute(decoder_kernel,
                         cudaFuncAttributeMaxDynamicSharedMemorySize, SM_TOTAL);
    decoder_kernel<<<2 * NGROUPS, 256, SM_TOTAL>>>(origins, directions, out);
}